// round 9
// baseline (speedup 1.0000x reference)
#include <cuda_runtime.h>
#include <math_constants.h>

// Roi_61564061221098 round 9: R8 + 128B-aligned repack.
//   pad_copy: x -> g_xpad with row stride 96 floats (384B = 3*128B), so every
//             row/plane is 128B-aligned. One-time ~67MB HBM (~9us).
//   roi_prep: window based at w0b = w0 & ~31 -> every lane-sweep LDG covers
//             exactly one 128B line (1 L1 wavefront instead of ~2).
//   roi_pool: warp = (roi, 8 channels); transposed scol [col][ch] written with
//             2x STS.128 per stripe. Reduce phase as R8 (lane = ch*4+slot,
//             each lane covers pw=slot and pw=slot+4).

#define NC     512
#define FH     50
#define FW     68
#define FW2    96
#define PLANE2 (FH * FW2)
#define PP     7
#define SCALE  0.0625f
#define NEG_INF (-CUDART_INF_F)

__device__ float g_xpad[4 * NC * PLANE2];         // 39.3 MB static scratch

// packed per-roi record: [0]=base(n*NC*PLANE2 + w0b), [1]=span(=we6-w0b),
// [2]=maxw, [3..9] = hs | he<<8 | (ws-w0b)<<16 | (we-w0b)<<24
__device__ __align__(16) int g_rec[4096 * 16];

__global__ void pad_copy(const float* __restrict__ x)
{
    const int e = blockIdx.x * 256 + threadIdx.x;     // index in padded space
    if (e >= 4 * NC * PLANE2) return;
    const int row = e / FW2;
    const int w   = e - row * FW2;
    if (w < FW) g_xpad[e] = x[row * FW + w];
}

__global__ void roi_prep(const float* __restrict__ rois,
                         const int*   __restrict__ ridx, int R)
{
    int r = blockIdx.x * blockDim.x + threadIdx.x;
    if (r >= R) return;

    const float y1 = rois[r * 4 + 0];
    const float x1 = rois[r * 4 + 1];
    const float y2 = rois[r * 4 + 2];
    const float x2 = rois[r * 4 + 3];
    const float rb0 = rintf(__fmul_rn(x1, SCALE));
    const float rb1 = rintf(__fmul_rn(y1, SCALE));
    const float rb2 = rintf(__fmul_rn(x2, SCALE));
    const float rb3 = rintf(__fmul_rn(y2, SCALE));
    const float roiw = fmaxf(__fadd_rn(__fsub_rn(rb2, rb0), 1.0f), 1.0f);
    const float roih = fmaxf(__fadd_rn(__fsub_rn(rb3, rb1), 1.0f), 1.0f);
    const float R7 = (float)(1.0 / 7.0);          // XLA: x/7 -> x * fl(1/7)
    const float bw = __fmul_rn(roiw, R7);
    const float bh = __fmul_rn(roih, R7);

    const int w0  = (int)fminf(fmaxf(rb0, 0.0f), (float)FW);  // == ws[0]
    const int w0b = w0 & ~31;                                 // 128B-aligned col base
    int maxw = 0;
    int pack[PP];
#pragma unroll
    for (int p = 0; p < PP; p++) {
        const float fp  = (float)p;
        const float fp1 = (float)(p + 1);
        int hs = (int)fminf(fmaxf(__fadd_rn(floorf(__fmul_rn(fp,  bh)), rb1), 0.0f), (float)FH);
        int he = (int)fminf(fmaxf(__fadd_rn(ceilf (__fmul_rn(fp1, bh)), rb1), 0.0f), (float)FH);
        int ws = (int)fminf(fmaxf(__fadd_rn(floorf(__fmul_rn(fp,  bw)), rb0), 0.0f), (float)FW);
        int we = (int)fminf(fmaxf(__fadd_rn(ceilf (__fmul_rn(fp1, bw)), rb0), 0.0f), (float)FW);
        maxw = max(maxw, we - ws);
        pack[p] = hs | (he << 8) | ((ws - w0b) << 16) | ((we - w0b) << 24);
    }
    int* rec = g_rec + r * 16;
    rec[0] = ridx[r] * (NC * PLANE2) + w0b;
    rec[1] = (pack[PP - 1] >> 24) & 0xff;     // span relative to w0b (<= 68)
    rec[2] = maxw;
#pragma unroll
    for (int p = 0; p < PP; p++) rec[3 + p] = pack[p];
}

template <int NR>
__device__ __forceinline__ void pool_warp(const float* __restrict__ fm,
                                          int v, int span, int maxw, int lane,
                                          float* __restrict__ scol,
                                          float* __restrict__ sout)
{
    const int ch   = lane >> 2;        // reduce-phase channel (0-7)
    const int slot = lane & 3;         // reduce-phase pw slot: pw = slot, slot+4
    const int pkA = __shfl_sync(0xffffffffu, v, 3 + slot);
    const int pkB = __shfl_sync(0xffffffffu, v, 3 + (slot < 3 ? slot + 4 : 6));
    const int j0a = (pkA >> 16) & 0xff, j1a = (pkA >> 24) & 0xff;
    const int j0b = (pkB >> 16) & 0xff, j1b = (pkB >> 24) & 0xff;

    bool act[NR];
#pragma unroll
    for (int q = 0; q < NR; q++) act[q] = (lane + q * 32) < span;

#pragma unroll
    for (int ph = 0; ph < PP; ph++) {
        const int pk = __shfl_sync(0xffffffffu, v, 3 + ph);
        const int h0 = pk & 0xff;
        const int h1 = (pk >> 8) & 0xff;

        float m[NR][8];
#pragma unroll
        for (int q = 0; q < NR; q++)
#pragma unroll
            for (int k = 0; k < 8; k++) m[q][k] = NEG_INF;

        const float* p = fm + h0 * FW2;
        for (int h = h0; h < h1; h++, p += FW2) {
#pragma unroll
            for (int q = 0; q < NR; q++) {
                if (act[q]) {                 // every LDG: one aligned 128B line
#pragma unroll
                    for (int k = 0; k < 8; k++)
                        m[q][k] = fmaxf(m[q][k], __ldg(p + lane + q * 32 + k * PLANE2));
                }
            }
        }

        // transposed column buffer: col stride 8 floats -> 2x STS.128 per stripe
#pragma unroll
        for (int q = 0; q < NR; q++) {
            float* c = scol + (lane + q * 32) * 8;
            *(float4*)(c)     = make_float4(m[q][0], m[q][1], m[q][2], m[q][3]);
            *(float4*)(c + 4) = make_float4(m[q][4], m[q][5], m[q][6], m[q][7]);
        }
        __syncwarp();

        // 8-channel-parallel per-pw reduce (each lane: pw=slot and pw=slot+4)
        float mmA = NEG_INF, mmB = NEG_INF;
        for (int k2 = 0; k2 < maxw; k2++) {
            const int jA = j0a + k2;
            const int jB = j0b + k2;
            if (jA < j1a) mmA = fmaxf(mmA, scol[jA * 8 + ch]);
            if (jB < j1b) mmB = fmaxf(mmB, scol[jB * 8 + ch]);
        }
        sout[ch * 49 + ph * PP + slot] = (mmA == NEG_INF) ? 0.0f : mmA;
        if (slot < 3)
            sout[ch * 49 + ph * PP + slot + 4] = (mmB == NEG_INF) ? 0.0f : mmB;
        __syncwarp();
    }
}

__global__ __launch_bounds__(256, 6)
void roi_pool(float* __restrict__ out, int R)
{
    __shared__ float s_col[8][96 * 8];      // 24 KB: transposed [col][ch]
    __shared__ float s_out[8][400];         // 12.8 KB

    const int r    = blockIdx.x;
    const int warp = threadIdx.x >> 5;
    const int lane = threadIdx.x & 31;
    const int c0   = blockIdx.y * 64 + warp * 8;   // 8 * 64 = 512 channels

    int v = 0;
    if (lane < 16) v = g_rec[r * 16 + lane];
    const int base = __shfl_sync(0xffffffffu, v, 0);
    const int span = __shfl_sync(0xffffffffu, v, 1);
    const int maxw = __shfl_sync(0xffffffffu, v, 2);

    const float* fm   = g_xpad + base + c0 * PLANE2;   // row 0, col w0b, channel c0
    float*       scol = s_col[warp];
    float*       sout = s_out[warp];

    if (span <= 32)      pool_warp<1>(fm, v, span, maxw, lane, scol, sout);
    else if (span <= 64) pool_warp<2>(fm, v, span, maxw, lane, scol, sout);
    else                 pool_warp<3>(fm, v, span, maxw, lane, scol, sout);

    // 392 contiguous floats per warp
    const long long ob = (long long)r * (NC * 49) + (long long)c0 * 49;
#pragma unroll
    for (int i = 0; i < 13; i++) {
        const int idx = i * 32 + lane;
        if (idx < 392) out[ob + idx] = sout[idx];
    }
}

extern "C" void kernel_launch(void* const* d_in, const int* in_sizes, int n_in,
                              void* d_out, int out_size)
{
    const float* x    = (const float*)d_in[0];
    const float* rois = (const float*)d_in[1];
    const int*   ridx = (const int*)d_in[2];
    float*       out  = (float*)d_out;
    const int R = in_sizes[2];

    pad_copy<<<(4 * NC * PLANE2 + 255) / 256, 256>>>(x);
    roi_prep<<<(R + 255) / 256, 256>>>(rois, ridx, R);
    dim3 grid(R, NC / 64);
    roi_pool<<<grid, 256>>>(out, R);
}